// round 15
// baseline (speedup 1.0000x reference)
#include <cuda_runtime.h>
#include <cuda_fp16.h>
#include <cstdint>

#define B_   2048
#define S_   512
#define DIN  5
#define H_   64
#define CC   32
#define EDIM 32
#define NEMB 64

// ---------------- static device scratch ----------------
__device__ __align__(16) float g_convout[(size_t)S_*B_*CC];   // [S][B][32]
__device__ __align__(16) float g_xT[(size_t)S_*B_*8];         // [S][B][5] stride 5
__device__ __align__(16) float g_ys_cnn[(size_t)S_*B_*H_];
__device__ __align__(16) float g_ys_vq[(size_t)S_*B_*H_];
__device__ __align__(16) float g_cnn_feat[B_*H_];
__device__ __align__(16) float g_vq_hid[B_*H_];
__device__ float g_sqsum;
__device__ int   g_counts[NEMB];

// ---------------- helpers ----------------
__device__ __forceinline__ float tanhapx(float x){
    float y; asm("tanh.approx.f32 %0, %1;" : "=f"(y) : "f"(x)); return y;
}
// pre-scaled sigmoid: caller provides 0.5*x (folded into weights/bias)
__device__ __forceinline__ float sig_ps(float xhalf){ return fmaf(0.5f, tanhapx(xhalf), 0.5f); }

__device__ __forceinline__ uint32_t smem_u32(const void* p){
    uint32_t a; asm("{ .reg .u64 t; cvta.to.shared.u64 t, %1; cvt.u32.u64 %0, t; }" : "=r"(a) : "l"(p)); return a;
}
__device__ __forceinline__ void ldsm4(uint32_t* r, uint32_t addr){
    asm volatile("ldmatrix.sync.aligned.m8n8.x4.shared.b16 {%0,%1,%2,%3}, [%4];"
        : "=r"(r[0]), "=r"(r[1]), "=r"(r[2]), "=r"(r[3]) : "r"(addr));
}
__device__ __forceinline__ void mma16816(float* c, const uint32_t* a, uint32_t b0, uint32_t b1){
    asm volatile("mma.sync.aligned.m16n8k16.row.col.f32.f16.f16.f32 "
        "{%0,%1,%2,%3}, {%4,%5,%6,%7}, {%8,%9}, {%0,%1,%2,%3};"
        : "+f"(c[0]), "+f"(c[1]), "+f"(c[2]), "+f"(c[3])
        : "r"(a[0]), "r"(a[1]), "r"(a[2]), "r"(a[3]), "r"(b0), "r"(b1));
}

#define STRD   136       // halves per X/A row
#define HBSTR  68        // floats per hbuf row
// smem byte layout
#define OFF_B0   0       // X tile buf0: hi [32][136] (8704B) + lo (8704B)
#define B_LOB    8704    // lo byte offset within a buffer
#define OFF_B1   17408
#define OFF_HB0  34816   // h fp32 [32][68] = 8704B
#define OFF_HB1  43520
#define OFF_AHI  52224   // [256][136] halves = 69632B
#define OFF_ALO  121856
#define SMEM_TOT 191488

// ---------------- prep: conv1d + BN + ReLU + transpose ----------------
__global__ void prep_kernel(const float* __restrict__ x, const float* __restrict__ conv_w,
                            const float* __restrict__ conv_b, const float* __restrict__ bn_g,
                            const float* __restrict__ bn_b, const float* __restrict__ bn_m,
                            const float* __restrict__ bn_v)
{
    __shared__ float ws[CC*15];
    __shared__ float bs[CC];
    int tid = threadIdx.x;
    for (int idx = tid; idx < CC*15; idx += 256){
        int c = idx / 15;
        float sc = bn_g[c] * rsqrtf(bn_v[c] + 1e-5f);
        ws[idx] = conv_w[idx] * sc;
    }
    if (tid < CC){
        float sc = bn_g[tid] * rsqrtf(bn_v[tid] + 1e-5f);
        bs[tid] = (conv_b[tid] - bn_m[tid]) * sc + bn_b[tid];
    }
    __syncthreads();

    int gid = blockIdx.x * 256 + tid;   // gid = b*S + s
    int s = gid & (S_-1);
    size_t xb = (size_t)gid * DIN;
    int b = gid >> 9;
    float x0[DIN], xm[DIN], xp[DIN];
    #pragma unroll
    for (int i = 0; i < DIN; i++){
        x0[i] = x[xb + i];
        xm[i] = (s > 0)    ? x[xb - DIN + i] : 0.f;
        xp[i] = (s < S_-1) ? x[xb + DIN + i] : 0.f;
    }
    float o[CC];
    #pragma unroll
    for (int c = 0; c < CC; c++){
        float acc = bs[c];
        #pragma unroll
        for (int i = 0; i < DIN; i++){
            acc = fmaf(xm[i], ws[c*15 + i*3 + 0], acc);
            acc = fmaf(x0[i], ws[c*15 + i*3 + 1], acc);
            acc = fmaf(xp[i], ws[c*15 + i*3 + 2], acc);
        }
        o[c] = fmaxf(acc, 0.f);
    }
    float4* dst = (float4*)&g_convout[((size_t)s*B_ + b)*CC];
    #pragma unroll
    for (int c = 0; c < CC/4; c++) dst[c] = make_float4(o[4*c], o[4*c+1], o[4*c+2], o[4*c+3]);
    float* xt = &g_xT[((size_t)s*B_ + b)*DIN];
    #pragma unroll
    for (int i = 0; i < DIN; i++) xt[i] = x0[i];
}

// ---------------- HMMA split-fp16 LSTM stream, fused-pipe schedule v2 ----------------
// 512 thr / 16 warps. Per step: xstore(t+1) -> barA -> h-GEMM(t) -> x-GEMM(t+1)
// back-to-back (tensor pipe never drains) -> shfl -> update -> barB.
// Register budget: only h-part A-hi fragments resident (ahi[HT][4]); x-part A
// fragments are re-loaded from smem inside xpart (latency hidden under update).
template<int XT, int HT, int KIN>
__device__ void lstm_stream(char* smem, const float* __restrict__ in_seq,
                            float* __restrict__ ys, float* __restrict__ hf, int row0,
                            const float* __restrict__ wih, const float* __restrict__ whh,
                            const float* __restrict__ bih, const float* __restrict__ bhh)
{
    const int tid  = threadIdx.x;
    const int lane = tid & 31;
    const int w    = tid >> 5;
    constexpr int KT   = XT + HT;
    constexpr int K    = KT * 16;
    constexpr int HOFF = XT * 16;
    const uint32_t sbase = smem_u32(smem);

    __half* Ahi = (__half*)(smem + OFF_AHI);
    __half* Alo = (__half*)(smem + OFF_ALO);

    // ---- stage split weights with gate-row permutation; scale I/F/O rows by 0.5 ----
    for (int idx = tid; idx < 256*K; idx += 512){
        int m = idx / K, k = idx - m*K;
        int ww = m >> 4, r = m & 15;
        int jcell = 4*ww + ((r & 7) >> 1);
        int gate  = (r < 8) ? (r & 1) : 2 + (r & 1);   // 0=I 1=F 2=G 3=O
        int n = gate*64 + jcell;
        float v = 0.f;
        if (k < KIN)                          v = wih[n*KIN + k];
        else if (k >= HOFF && k < HOFF + H_)  v = whh[n*H_ + (k - HOFF)];
        if (gate != 2) v *= 0.5f;
        __half hi = __float2half_rn(v);
        Ahi[m*STRD + k] = hi;
        Alo[m*STRD + k] = __float2half_rn(v - __half2float(hi));
    }
    // zero both X buffers
    for (int i = tid; i < 8704; i += 512) ((uint32_t*)smem)[i] = 0u;
    __syncthreads();

    // ---- A-hi fragments resident in registers: h-part tiles only ----
    uint32_t ahi[HT][4];
    const int arow = (w << 4) + (lane & 7) + (((lane >> 3) & 1) << 3);
    const uint32_t abh = smem_u32(Ahi) + (uint32_t)(arow * STRD) * 2u;
    const uint32_t abl = smem_u32(Alo) + (uint32_t)(arow * STRD) * 2u;
    #pragma unroll
    for (int kt = 0; kt < HT; kt++)
        ldsm4(ahi[kt], abh + (uint32_t)((XT+kt)*16 + ((lane >> 4) << 3)) * 2u);

    // per-thread roles
    const int gq  = lane >> 2, tig = lane & 3;
    const int sel = gq & 1;
    const int jc  = 4*w + (gq >> 1);
    const float bI = 0.5f*(bih[jc]      + bhh[jc]);
    const float bF = 0.5f*(bih[64+jc]   + bhh[64+jc]);
    const float bG =       bih[128+jc]  + bhh[128+jc];
    const float bO = 0.5f*(bih[192+jc]  + bhh[192+jc]);
    const int colbase = (sel ? 16 : 0) + 2*tig;
    const int bn = ((lane >> 4) << 3) + (lane & 7);
    const int bk = ((lane >> 3) & 1) << 3;
    const int frow = tid >> 4, fc0 = (tid & 15) << 2;
    float cst[4] = {0.f, 0.f, 0.f, 0.f};

    float xr0=0.f, xr1=0.f, xr2=0.f, xr3=0.f;

    auto xpref = [&](int t){
        if (KIN == 64){
            const float4 q = *(const float4*)&in_seq[((size_t)t*B_ + row0 + (tid>>4))*64 + ((tid&15)<<2)];
            xr0=q.x; xr1=q.y; xr2=q.z; xr3=q.w;
        } else if (KIN == 32){
            const float2 q = *(const float2*)&in_seq[((size_t)t*B_ + row0 + (tid>>4))*32 + ((tid&15)<<1)];
            xr0=q.x; xr1=q.y;
        } else {
            if (tid < 32*KIN)
                xr0 = in_seq[((size_t)t*B_ + row0 + tid/KIN)*KIN + (tid - (tid/KIN)*KIN)];
        }
    };
    auto xstore = [&](char* bdst){
        __half* BhN = (__half*)bdst;
        __half* BlN = (__half*)(bdst + B_LOB);
        if (KIN == 64){
            int r = tid >> 4, c0 = (tid & 15) << 2;
            __half h0=__float2half_rn(xr0), h1=__float2half_rn(xr1);
            __half h2=__float2half_rn(xr2), h3=__float2half_rn(xr3);
            *(__half2*)&BhN[r*STRD + c0]     = __half2(h0,h1);
            *(__half2*)&BhN[r*STRD + c0 + 2] = __half2(h2,h3);
            *(__half2*)&BlN[r*STRD + c0]     =
                __half2(__float2half_rn(xr0-__half2float(h0)), __float2half_rn(xr1-__half2float(h1)));
            *(__half2*)&BlN[r*STRD + c0 + 2] =
                __half2(__float2half_rn(xr2-__half2float(h2)), __float2half_rn(xr3-__half2float(h3)));
        } else if (KIN == 32){
            int r = tid >> 4, c0 = (tid & 15) << 1;
            __half h0=__float2half_rn(xr0), h1=__float2half_rn(xr1);
            *(__half2*)&BhN[r*STRD + c0] = __half2(h0, h1);
            *(__half2*)&BlN[r*STRD + c0] =
                __half2(__float2half_rn(xr0-__half2float(h0)), __float2half_rn(xr1-__half2float(h1)));
        } else {
            if (tid < 32*KIN){
                int r = tid / KIN, k = tid - r*KIN;
                __half h0 = __float2half_rn(xr0);
                BhN[r*STRD + k] = h0;
                BlN[r*STRD + k] = __float2half_rn(xr0 - __half2float(h0));
            }
        }
    };
    auto mma12 = [&](float (&c)[4][4], const uint32_t* ah, const uint32_t* al,
                     const uint32_t* xh0, const uint32_t* xh1,
                     const uint32_t* xl0, const uint32_t* xl1){
        mma16816(c[0], ah, xh0[0], xh0[1]);
        mma16816(c[1], ah, xh0[2], xh0[3]);
        mma16816(c[2], ah, xh1[0], xh1[1]);
        mma16816(c[3], ah, xh1[2], xh1[3]);
        mma16816(c[0], ah, xl0[0], xl0[1]);
        mma16816(c[1], ah, xl0[2], xl0[3]);
        mma16816(c[2], ah, xl1[0], xl1[1]);
        mma16816(c[3], ah, xl1[2], xl1[3]);
        mma16816(c[0], al, xh0[0], xh0[1]);
        mma16816(c[1], al, xh0[2], xh0[3]);
        mma16816(c[2], al, xh1[0], xh1[1]);
        mma16816(c[3], al, xh1[2], xh1[3]);
    };
    // x-part GEMM: A fragments loaded from smem (latency hidden under update)
    auto xpart = [&](float (&cA)[4][4], uint32_t boff){
        #pragma unroll
        for (int nt = 0; nt < 4; nt++){ cA[nt][0]=0.f; cA[nt][1]=0.f; cA[nt][2]=0.f; cA[nt][3]=0.f; }
        const uint32_t h0 = sbase + boff + (uint32_t)(bn*STRD + bk)*2u;
        const uint32_t h1 = h0 + 16u*STRD*2u;
        const uint32_t l0 = h0 + B_LOB, l1 = h1 + B_LOB;
        #pragma unroll
        for (int kt = 0; kt < XT; kt++){
            const uint32_t ko = (uint32_t)kt * 32u;
            const uint32_t ao = (uint32_t)(kt*16 + ((lane >> 4) << 3)) * 2u;
            uint32_t xh0[4], xh1[4], xl0[4], xl1[4], ah[4], al[4];
            ldsm4(xh0, h0 + ko); ldsm4(xh1, h1 + ko);
            ldsm4(xl0, l0 + ko); ldsm4(xl1, l1 + ko);
            ldsm4(ah, abh + ao);
            ldsm4(al, abl + ao);
            mma12(cA, ah, al, xh0, xh1, xl0, xl1);
        }
    };

    // ---- prime: x(0) -> buf0, xr <- x(1), c0 <- x-part(t=0) ----
    {
        __half* Bh = (__half*)(smem + OFF_B0);
        __half* Bl = (__half*)(smem + OFF_B0 + B_LOB);
        for (int idx = tid; idx < 32*KIN; idx += 512){
            int r = idx / KIN, k = idx - r*KIN;
            float v = in_seq[((size_t)row0 + r)*KIN + k];
            __half hi = __float2half_rn(v);
            Bh[r*STRD + k] = hi;
            Bl[r*STRD + k] = __float2half_rn(v - __half2float(hi));
        }
    }
    xpref(1);
    __syncthreads();
    float c0[4][4], c1[4][4];
    xpart(c0, OFF_B0);

    auto stepf = [&](int t, float (&cU)[4][4], float (&cA)[4][4]){
        const int p = t & 1;
        const uint32_t curoff = p ? OFF_B1 : OFF_B0;
        const uint32_t nxtoff = p ? OFF_B0 : OFF_B1;
        char* bnext = smem + nxtoff;
        float* hbW = (float*)(smem + (p ? OFF_HB1 : OFF_HB0));

        // ---- publish x(t+1) to next buffer FIRST (frees xr), then barrier ----
        if (t + 1 < S_) xstore(bnext);
        __syncthreads();   // barA

        // stream ys(t-1) (overlaps GEMMs)
        if (ys && t > 0){
            const float* hbR = (const float*)(smem + (p ? OFF_HB0 : OFF_HB1));
            float4 v = *(const float4*)&hbR[frow*HBSTR + fc0];
            *(float4*)&ys[((size_t)(t-1)*B_ + row0 + frow)*H_ + fc0] = v;
        }

        // ---- h-part GEMM for step t (A-hi in registers) ----
        {
            const uint32_t h0 = sbase + curoff + (uint32_t)(bn*STRD + bk)*2u;
            const uint32_t h1 = h0 + 16u*STRD*2u;
            const uint32_t l0 = h0 + B_LOB, l1 = h1 + B_LOB;
            #pragma unroll
            for (int kt = 0; kt < HT; kt++){
                const int kk = XT + kt;
                const uint32_t ko = (uint32_t)kk * 32u;
                uint32_t xh0[4], xh1[4], xl0[4], xl1[4], alo[4];
                ldsm4(xh0, h0 + ko); ldsm4(xh1, h1 + ko);
                ldsm4(xl0, l0 + ko); ldsm4(xl1, l1 + ko);
                ldsm4(alo, abl + (uint32_t)(kk*16 + ((lane >> 4) << 3)) * 2u);
                mma12(cU, ahi[kt], alo, xh0, xh1, xl0, xl1);
            }
        }

        // ---- x-part GEMM for t+1, back-to-back: tensor pipe never drains ----
        if (t + 1 < S_) xpart(cA, nxtoff);
        if (t + 2 < S_) xpref(t + 2);

        // ---- lane^4 exchange of exactly the half the partner needs ----
        float xc2[2][4];
        #pragma unroll
        for (int u = 0; u < 2; u++)
            #pragma unroll
            for (int q = 0; q < 4; q++)
                xc2[u][q] = __shfl_xor_sync(0xffffffffu, sel ? cU[u][q] : cU[u+2][q], 4);

        // ---- update 4 cells ----
        __half* BhN = (__half*)bnext;
        __half* BlN = (__half*)(bnext + B_LOB);
        #pragma unroll
        for (int u = 0; u < 2; u++){
            #pragma unroll
            for (int pp = 0; pp < 2; pp++){
                float own0 = sel ? cU[u+2][pp]    : cU[u][pp];
                float own2 = sel ? cU[u+2][2+pp]  : cU[u][2+pp];
                float oth0 = xc2[u][pp];
                float oth2 = xc2[u][2+pp];
                float gi = (sel ? oth0 : own0) + bI;
                float gf = (sel ? own0 : oth0) + bF;
                float gg = (sel ? oth2 : own2) + bG;
                float go = (sel ? own2 : oth2) + bO;
                int li = u*2 + pp;
                float cc = sig_ps(gf)*cst[li] + sig_ps(gi)*tanhapx(gg);
                cst[li] = cc;
                float h = sig_ps(go)*tanhapx(cc);
                int col = colbase + u*8 + pp;
                __half hh = __float2half_rn(h);
                BhN[col*STRD + HOFF + jc] = hh;
                BlN[col*STRD + HOFF + jc] = __float2half_rn(h - __half2float(hh));
                if (ys) hbW[col*HBSTR + jc] = h;
                if (hf && t == S_-1) hf[(row0 + col)*H_ + jc] = h;
            }
        }
        __syncthreads();   // barB
    };

    for (int t = 0; t < S_; t += 2){
        stepf(t,     c0, c1);
        stepf(t + 1, c1, c0);
    }

    // final ys flush (step S-1 wrote hb[(S-1)&1] = HB1)
    if (ys){
        const float* hbR = (const float*)(smem + OFF_HB1);
        float4 v = *(const float4*)&hbR[frow*HBSTR + fc0];
        *(float4*)&ys[((size_t)(S_-1)*B_ + row0 + frow)*H_ + fc0] = v;
    }
}

__global__ void __launch_bounds__(512, 1) lstm_l0(
    const float* __restrict__ c_wih, const float* __restrict__ c_whh,
    const float* __restrict__ c_bih, const float* __restrict__ c_bhh,
    const float* __restrict__ v_wih, const float* __restrict__ v_whh,
    const float* __restrict__ v_bih, const float* __restrict__ v_bhh)
{
    extern __shared__ char smem[];
    if (blockIdx.x < 64)
        lstm_stream<2, 4, CC>(smem, g_convout, g_ys_cnn, nullptr, blockIdx.x*32,
                              c_wih, c_whh, c_bih, c_bhh);
    else
        lstm_stream<1, 4, DIN>(smem, g_xT, g_ys_vq, nullptr, (blockIdx.x-64)*32,
                               v_wih, v_whh, v_bih, v_bhh);
}

__global__ void __launch_bounds__(512, 1) lstm_l1(
    const float* __restrict__ c_wih, const float* __restrict__ c_whh,
    const float* __restrict__ c_bih, const float* __restrict__ c_bhh,
    const float* __restrict__ v_wih, const float* __restrict__ v_whh,
    const float* __restrict__ v_bih, const float* __restrict__ v_bhh)
{
    extern __shared__ char smem[];
    if (blockIdx.x < 64)
        lstm_stream<4, 4, H_>(smem, g_ys_cnn, nullptr, g_cnn_feat, blockIdx.x*32,
                              c_wih, c_whh, c_bih, c_bhh);
    else
        lstm_stream<4, 4, H_>(smem, g_ys_vq, nullptr, g_vq_hid, (blockIdx.x-64)*32,
                              v_wih, v_whh, v_bih, v_bhh);
}

// ---------------- VQ epilogue ----------------
__global__ void zero_k(){
    int t = threadIdx.x;
    if (t < NEMB) g_counts[t] = 0;
    if (t == 0)   g_sqsum = 0.f;
}

__global__ void vq_final(const float* __restrict__ proj_w, const float* __restrict__ proj_b,
                         const float* __restrict__ codebook, float* __restrict__ out)
{
    __shared__ float pw[EDIM*H_];
    __shared__ float pb[EDIM];
    __shared__ float cb[NEMB*EDIM];
    __shared__ float cn2[NEMB];
    __shared__ float red[256];
    int tid = threadIdx.x;
    for (int i = tid; i < EDIM*H_;   i += 256) pw[i] = proj_w[i];
    for (int i = tid; i < NEMB*EDIM; i += 256) cb[i] = codebook[i];
    if (tid < EDIM) pb[tid] = proj_b[tid];
    __syncthreads();
    if (tid < NEMB){
        float s = 0.f;
        #pragma unroll
        for (int e = 0; e < EDIM; e++){ float v = cb[tid*EDIM + e]; s = fmaf(v, v, s); }
        cn2[tid] = s;
    }
    __syncthreads();

    int b = blockIdx.x*256 + tid;
    float h[H_];
    const float4* hp = (const float4*)&g_vq_hid[b*H_];
    #pragma unroll
    for (int i = 0; i < H_/4; i++){
        float4 v = hp[i]; h[4*i] = v.x; h[4*i+1] = v.y; h[4*i+2] = v.z; h[4*i+3] = v.w;
    }
    float p[EDIM]; float p2 = 0.f;
    #pragma unroll
    for (int e = 0; e < EDIM; e++){
        float a = pb[e];
        #pragma unroll
        for (int d = 0; d < H_; d++) a = fmaf(pw[e*H_ + d], h[d], a);
        p[e] = a; p2 = fmaf(a, a, p2);
    }
    int best = 0; float dmin = 3.4e38f;
    #pragma unroll 4
    for (int n = 0; n < NEMB; n++){
        float dot = 0.f;
        #pragma unroll
        for (int e = 0; e < EDIM; e++) dot = fmaf(cb[n*EDIM + e], p[e], dot);
        float d = p2 + cn2[n] - 2.f*dot;
        if (d < dmin){ dmin = d; best = n; }
    }
    float rs = 0.f;
    #pragma unroll
    for (int e = 0; e < EDIM; e++){ float r = cb[best*EDIM + e] - p[e]; rs = fmaf(r, r, rs); }
    red[tid] = rs;
    atomicAdd(&g_counts[best], 1);

    const float* cf = &g_cnn_feat[b*H_];
    float* o0 = out + (size_t)b*96;
    float* o1 = out + (size_t)B_*96 + (size_t)b*96;
    #pragma unroll
    for (int jj = 0; jj < H_; jj++){ float v = cf[jj]; o0[jj] = v; o1[jj] = v; }
    #pragma unroll
    for (int e = 0; e < EDIM; e++){ float v = cb[best*EDIM + e]; o0[H_+e] = v; o1[H_+e] = v; }

    __syncthreads();
    for (int st = 128; st > 0; st >>= 1){
        if (tid < st) red[tid] += red[tid + st];
        __syncthreads();
    }
    if (tid == 0) atomicAdd(&g_sqsum, red[0]);
}

__global__ void finalize_k(float* __restrict__ out){
    if (threadIdx.x == 0){
        float msq = g_sqsum / (float)(B_*EDIM);
        out[(size_t)2*B_*96]     = msq + 0.01f * msq;
        float ent = 0.f;
        for (int n = 0; n < NEMB; n++){
            float ap = (float)g_counts[n] / (float)B_;
            ent += ap * logf(ap + 1e-10f);
        }
        out[(size_t)2*B_*96 + 1] = expf(-ent);
    }
}

// ---------------- launch ----------------
extern "C" void kernel_launch(void* const* d_in, const int* in_sizes, int n_in,
                              void* d_out, int out_size)
{
    const float* x       = (const float*)d_in[0];
    const float* conv_w  = (const float*)d_in[1];
    const float* conv_b  = (const float*)d_in[2];
    const float* bn_g    = (const float*)d_in[3];
    const float* bn_b    = (const float*)d_in[4];
    const float* bn_m    = (const float*)d_in[5];
    const float* bn_v    = (const float*)d_in[6];
    const float* c0_wih  = (const float*)d_in[7];
    const float* c0_whh  = (const float*)d_in[8];
    const float* c0_bih  = (const float*)d_in[9];
    const float* c0_bhh  = (const float*)d_in[10];
    const float* c1_wih  = (const float*)d_in[11];
    const float* c1_whh  = (const float*)d_in[12];
    const float* c1_bih  = (const float*)d_in[13];
    const float* c1_bhh  = (const float*)d_in[14];
    const float* v0_wih  = (const float*)d_in[15];
    const float* v0_whh  = (const float*)d_in[16];
    const float* v0_bih  = (const float*)d_in[17];
    const float* v0_bhh  = (const float*)d_in[18];
    const float* v1_wih  = (const float*)d_in[19];
    const float* v1_whh  = (const float*)d_in[20];
    const float* v1_bih  = (const float*)d_in[21];
    const float* v1_bhh  = (const float*)d_in[22];
    const float* proj_w  = (const float*)d_in[23];
    const float* proj_b  = (const float*)d_in[24];
    const float* codebook= (const float*)d_in[25];
    float* out = (float*)d_out;

    cudaFuncSetAttribute(lstm_l0, cudaFuncAttributeMaxDynamicSharedMemorySize, SMEM_TOT);
    cudaFuncSetAttribute(lstm_l1, cudaFuncAttributeMaxDynamicSharedMemorySize, SMEM_TOT);

    prep_kernel<<<(B_*S_)/256, 256>>>(x, conv_w, conv_b, bn_g, bn_b, bn_m, bn_v);
    zero_k<<<1, 64>>>();
    lstm_l0<<<128, 512, SMEM_TOT>>>(c0_wih, c0_whh, c0_bih, c0_bhh,
                                    v0_wih, v0_whh, v0_bih, v0_bhh);
    lstm_l1<<<128, 512, SMEM_TOT>>>(c1_wih, c1_whh, c1_bih, c1_bhh,
                                    v1_wih, v1_whh, v1_bih, v1_bhh);
    vq_final<<<B_/256, 256>>>(proj_w, proj_b, codebook, out);
    finalize_k<<<1, 64>>>(out);
}

// round 16
// speedup vs baseline: 1.2248x; 1.2248x over previous
#include <cuda_runtime.h>
#include <cuda_fp16.h>
#include <cstdint>

#define B_   2048
#define S_   512
#define DIN  5
#define H_   64
#define CC   32
#define EDIM 32
#define NEMB 64

// ---------------- static device scratch ----------------
__device__ __align__(16) float g_convout[(size_t)S_*B_*CC];   // [S][B][32]
__device__ __align__(16) float g_xT[(size_t)S_*B_*8];         // [S][B][5] stride 5
__device__ __align__(16) float g_ys_cnn[(size_t)S_*B_*H_];
__device__ __align__(16) float g_ys_vq[(size_t)S_*B_*H_];
__device__ __align__(16) float g_cnn_feat[B_*H_];
__device__ __align__(16) float g_vq_hid[B_*H_];
__device__ float g_sqsum;
__device__ int   g_counts[NEMB];

// ---------------- helpers ----------------
__device__ __forceinline__ float tanhapx(float x){
    float y; asm("tanh.approx.f32 %0, %1;" : "=f"(y) : "f"(x)); return y;
}
// pre-scaled sigmoid: caller provides 0.5*x (folded into weights/bias)
__device__ __forceinline__ float sig_ps(float xhalf){ return fmaf(0.5f, tanhapx(xhalf), 0.5f); }

__device__ __forceinline__ uint32_t smem_u32(const void* p){
    uint32_t a; asm("{ .reg .u64 t; cvta.to.shared.u64 t, %1; cvt.u32.u64 %0, t; }" : "=r"(a) : "l"(p)); return a;
}
__device__ __forceinline__ void ldsm4(uint32_t* r, uint32_t addr){
    asm volatile("ldmatrix.sync.aligned.m8n8.x4.shared.b16 {%0,%1,%2,%3}, [%4];"
        : "=r"(r[0]), "=r"(r[1]), "=r"(r[2]), "=r"(r[3]) : "r"(addr));
}
__device__ __forceinline__ void mma16816(float* c, const uint32_t* a, uint32_t b0, uint32_t b1){
    asm volatile("mma.sync.aligned.m16n8k16.row.col.f32.f16.f16.f32 "
        "{%0,%1,%2,%3}, {%4,%5,%6,%7}, {%8,%9}, {%0,%1,%2,%3};"
        : "+f"(c[0]), "+f"(c[1]), "+f"(c[2]), "+f"(c[3])
        : "r"(a[0]), "r"(a[1]), "r"(a[2]), "r"(a[3]), "r"(b0), "r"(b1));
}

#define STRD   136       // halves per X/A row
#define HBSTR  68        // floats per hbuf row
// smem byte layout
#define OFF_B0   0       // X tile buf0: hi [32][136] (8704B) + lo (8704B)
#define B_LOB    8704    // lo byte offset within a buffer
#define OFF_B1   17408
#define OFF_HB0  34816   // h fp32 [32][68] = 8704B
#define OFF_HB1  43520
#define OFF_AHI  52224   // [256][136] halves = 69632B
#define OFF_ALO  121856
#define SMEM_TOT 191488

// ---------------- prep: conv1d + BN + ReLU + transpose ----------------
__global__ void prep_kernel(const float* __restrict__ x, const float* __restrict__ conv_w,
                            const float* __restrict__ conv_b, const float* __restrict__ bn_g,
                            const float* __restrict__ bn_b, const float* __restrict__ bn_m,
                            const float* __restrict__ bn_v)
{
    __shared__ float ws[CC*15];
    __shared__ float bs[CC];
    int tid = threadIdx.x;
    for (int idx = tid; idx < CC*15; idx += 256){
        int c = idx / 15;
        float sc = bn_g[c] * rsqrtf(bn_v[c] + 1e-5f);
        ws[idx] = conv_w[idx] * sc;
    }
    if (tid < CC){
        float sc = bn_g[tid] * rsqrtf(bn_v[tid] + 1e-5f);
        bs[tid] = (conv_b[tid] - bn_m[tid]) * sc + bn_b[tid];
    }
    __syncthreads();

    int gid = blockIdx.x * 256 + tid;   // gid = b*S + s
    int s = gid & (S_-1);
    size_t xb = (size_t)gid * DIN;
    int b = gid >> 9;
    float x0[DIN], xm[DIN], xp[DIN];
    #pragma unroll
    for (int i = 0; i < DIN; i++){
        x0[i] = x[xb + i];
        xm[i] = (s > 0)    ? x[xb - DIN + i] : 0.f;
        xp[i] = (s < S_-1) ? x[xb + DIN + i] : 0.f;
    }
    float o[CC];
    #pragma unroll
    for (int c = 0; c < CC; c++){
        float acc = bs[c];
        #pragma unroll
        for (int i = 0; i < DIN; i++){
            acc = fmaf(xm[i], ws[c*15 + i*3 + 0], acc);
            acc = fmaf(x0[i], ws[c*15 + i*3 + 1], acc);
            acc = fmaf(xp[i], ws[c*15 + i*3 + 2], acc);
        }
        o[c] = fmaxf(acc, 0.f);
    }
    float4* dst = (float4*)&g_convout[((size_t)s*B_ + b)*CC];
    #pragma unroll
    for (int c = 0; c < CC/4; c++) dst[c] = make_float4(o[4*c], o[4*c+1], o[4*c+2], o[4*c+3]);
    float* xt = &g_xT[((size_t)s*B_ + b)*DIN];
    #pragma unroll
    for (int i = 0; i < DIN; i++) xt[i] = x0[i];
}

// ---------------- HMMA split-fp16 LSTM stream (R14 schedule; x-part 2-term) ----------------
// 512 thr / 16 warps. A rows permuted; lane^4 shfl exchanges exactly the half of C
// each partner needs. x-part GEMM of step t+1 retires under the update.
// h-part: full 3-term split (Ahi*Bhi + Ahi*Blo + Alo*Bhi) — recurrence-critical.
// x-part: 2-term (Ahi*Bhi + Alo*Bhi) — x's fp16 residual error does not compound.
template<int XT, int HT, int KIN>
__device__ void lstm_stream(char* smem, const float* __restrict__ in_seq,
                            float* __restrict__ ys, float* __restrict__ hf, int row0,
                            const float* __restrict__ wih, const float* __restrict__ whh,
                            const float* __restrict__ bih, const float* __restrict__ bhh)
{
    const int tid  = threadIdx.x;
    const int lane = tid & 31;
    const int w    = tid >> 5;
    constexpr int KT   = XT + HT;
    constexpr int K    = KT * 16;
    constexpr int HOFF = XT * 16;
    const uint32_t sbase = smem_u32(smem);

    __half* Ahi = (__half*)(smem + OFF_AHI);
    __half* Alo = (__half*)(smem + OFF_ALO);

    // ---- stage split weights with gate-row permutation; scale I/F/O rows by 0.5 ----
    for (int idx = tid; idx < 256*K; idx += 512){
        int m = idx / K, k = idx - m*K;
        int ww = m >> 4, r = m & 15;
        int jcell = 4*ww + ((r & 7) >> 1);
        int gate  = (r < 8) ? (r & 1) : 2 + (r & 1);   // 0=I 1=F 2=G 3=O
        int n = gate*64 + jcell;
        float v = 0.f;
        if (k < KIN)                          v = wih[n*KIN + k];
        else if (k >= HOFF && k < HOFF + H_)  v = whh[n*H_ + (k - HOFF)];
        if (gate != 2) v *= 0.5f;
        __half hi = __float2half_rn(v);
        Ahi[m*STRD + k] = hi;
        Alo[m*STRD + k] = __float2half_rn(v - __half2float(hi));
    }
    // zero both X buffers (x-lo region stays zero forever; h-lo written per step)
    for (int i = tid; i < 8704; i += 512) ((uint32_t*)smem)[i] = 0u;
    __syncthreads();

    // ---- A-hi fragments resident in registers (all KT tiles, as in R14) ----
    uint32_t ahi[KT][4];
    const int arow = (w << 4) + (lane & 7) + (((lane >> 3) & 1) << 3);
    const uint32_t abh = smem_u32(Ahi) + (uint32_t)(arow * STRD) * 2u;
    const uint32_t abl = smem_u32(Alo) + (uint32_t)(arow * STRD) * 2u;
    #pragma unroll
    for (int kt = 0; kt < KT; kt++)
        ldsm4(ahi[kt], abh + (uint32_t)(kt*16 + ((lane >> 4) << 3)) * 2u);

    // per-thread roles
    const int gq  = lane >> 2, tig = lane & 3;
    const int sel = gq & 1;
    const int jc  = 4*w + (gq >> 1);
    const float bI = 0.5f*(bih[jc]      + bhh[jc]);
    const float bF = 0.5f*(bih[64+jc]   + bhh[64+jc]);
    const float bG =       bih[128+jc]  + bhh[128+jc];
    const float bO = 0.5f*(bih[192+jc]  + bhh[192+jc]);
    const int colbase = (sel ? 16 : 0) + 2*tig;
    const int bn = ((lane >> 4) << 3) + (lane & 7);
    const int bk = ((lane >> 3) & 1) << 3;
    const int frow = tid >> 4, fc0 = (tid & 15) << 2;
    float cst[4] = {0.f, 0.f, 0.f, 0.f};

    float xr0=0.f, xr1=0.f, xr2=0.f, xr3=0.f;

    auto xpref = [&](int t){
        if (KIN == 64){
            const float4 q = *(const float4*)&in_seq[((size_t)t*B_ + row0 + (tid>>4))*64 + ((tid&15)<<2)];
            xr0=q.x; xr1=q.y; xr2=q.z; xr3=q.w;
        } else if (KIN == 32){
            const float2 q = *(const float2*)&in_seq[((size_t)t*B_ + row0 + (tid>>4))*32 + ((tid&15)<<1)];
            xr0=q.x; xr1=q.y;
        } else {
            if (tid < 32*KIN)
                xr0 = in_seq[((size_t)t*B_ + row0 + tid/KIN)*KIN + (tid - (tid/KIN)*KIN)];
        }
    };
    // x stored hi-only (2-term x-part never reads x-lo; region stays zero)
    auto xstore = [&](char* bdst){
        __half* BhN = (__half*)bdst;
        if (KIN == 64){
            int r = tid >> 4, c0 = (tid & 15) << 2;
            *(__half2*)&BhN[r*STRD + c0]     = __half2(__float2half_rn(xr0), __float2half_rn(xr1));
            *(__half2*)&BhN[r*STRD + c0 + 2] = __half2(__float2half_rn(xr2), __float2half_rn(xr3));
        } else if (KIN == 32){
            int r = tid >> 4, c0 = (tid & 15) << 1;
            *(__half2*)&BhN[r*STRD + c0] = __half2(__float2half_rn(xr0), __float2half_rn(xr1));
        } else {
            if (tid < 32*KIN){
                int r = tid / KIN, k = tid - r*KIN;
                BhN[r*STRD + k] = __float2half_rn(xr0);
            }
        }
    };
    auto mma12 = [&](float (&c)[4][4], const uint32_t* ah, const uint32_t* al,
                     const uint32_t* xh0, const uint32_t* xh1,
                     const uint32_t* xl0, const uint32_t* xl1){
        mma16816(c[0], ah, xh0[0], xh0[1]);
        mma16816(c[1], ah, xh0[2], xh0[3]);
        mma16816(c[2], ah, xh1[0], xh1[1]);
        mma16816(c[3], ah, xh1[2], xh1[3]);
        mma16816(c[0], ah, xl0[0], xl0[1]);
        mma16816(c[1], ah, xl0[2], xl0[3]);
        mma16816(c[2], ah, xl1[0], xl1[1]);
        mma16816(c[3], ah, xl1[2], xl1[3]);
        mma16816(c[0], al, xh0[0], xh0[1]);
        mma16816(c[1], al, xh0[2], xh0[3]);
        mma16816(c[2], al, xh1[0], xh1[1]);
        mma16816(c[3], al, xh1[2], xh1[3]);
    };
    // x-part: 2-term (no B-lo), 8 MMAs + 2 x-ldsm per k-tile
    auto xpart = [&](float (&cA)[4][4], uint32_t boff){
        #pragma unroll
        for (int nt = 0; nt < 4; nt++){ cA[nt][0]=0.f; cA[nt][1]=0.f; cA[nt][2]=0.f; cA[nt][3]=0.f; }
        const uint32_t h0 = sbase + boff + (uint32_t)(bn*STRD + bk)*2u;
        const uint32_t h1 = h0 + 16u*STRD*2u;
        #pragma unroll
        for (int kt = 0; kt < XT; kt++){
            const uint32_t ko = (uint32_t)kt * 32u;
            uint32_t xh0[4], xh1[4], alo[4];
            ldsm4(xh0, h0 + ko); ldsm4(xh1, h1 + ko);
            ldsm4(alo, abl + (uint32_t)(kt*16 + ((lane >> 4) << 3)) * 2u);
            mma16816(cA[0], ahi[kt], xh0[0], xh0[1]);
            mma16816(cA[1], ahi[kt], xh0[2], xh0[3]);
            mma16816(cA[2], ahi[kt], xh1[0], xh1[1]);
            mma16816(cA[3], ahi[kt], xh1[2], xh1[3]);
            mma16816(cA[0], alo, xh0[0], xh0[1]);
            mma16816(cA[1], alo, xh0[2], xh0[3]);
            mma16816(cA[2], alo, xh1[0], xh1[1]);
            mma16816(cA[3], alo, xh1[2], xh1[3]);
        }
    };

    // ---- prime: x(0) -> buf0, xr <- x(1), c0 <- x-part(t=0) ----
    {
        __half* Bh = (__half*)(smem + OFF_B0);
        for (int idx = tid; idx < 32*KIN; idx += 512){
            int r = idx / KIN, k = idx - r*KIN;
            Bh[r*STRD + k] = __float2half_rn(in_seq[((size_t)row0 + r)*KIN + k]);
        }
    }
    xpref(1);
    __syncthreads();
    float c0[4][4], c1[4][4];
    xpart(c0, OFF_B0);

    auto stepf = [&](int t, float (&cU)[4][4], float (&cA)[4][4]){
        const int p = t & 1;
        const uint32_t curoff = p ? OFF_B1 : OFF_B0;
        const uint32_t nxtoff = p ? OFF_B0 : OFF_B1;
        char* bnext = smem + nxtoff;
        float* hbW = (float*)(smem + (p ? OFF_HB1 : OFF_HB0));

        // stream ys(t-1) (overlaps h-part GEMM)
        if (ys && t > 0){
            const float* hbR = (const float*)(smem + (p ? OFF_HB0 : OFF_HB1));
            float4 v = *(const float4*)&hbR[frow*HBSTR + fc0];
            *(float4*)&ys[((size_t)(t-1)*B_ + row0 + frow)*H_ + fc0] = v;
        }

        // ---- h-part GEMM for step t (3-term) ----
        {
            const uint32_t h0 = sbase + curoff + (uint32_t)(bn*STRD + bk)*2u;
            const uint32_t h1 = h0 + 16u*STRD*2u;
            const uint32_t l0 = h0 + B_LOB, l1 = h1 + B_LOB;
            #pragma unroll
            for (int kt = 0; kt < HT; kt++){
                const int kk = XT + kt;
                const uint32_t ko = (uint32_t)kk * 32u;
                uint32_t xh0[4], xh1[4], xl0[4], xl1[4], alo[4];
                ldsm4(xh0, h0 + ko); ldsm4(xh1, h1 + ko);
                ldsm4(xl0, l0 + ko); ldsm4(xl1, l1 + ko);
                ldsm4(alo, abl + (uint32_t)(kk*16 + ((lane >> 4) << 3)) * 2u);
                mma12(cU, ahi[kk], alo, xh0, xh1, xl0, xl1);
            }
        }

        // ---- lane^4 exchange of exactly the half the partner needs ----
        float xc2[2][4];
        #pragma unroll
        for (int u = 0; u < 2; u++)
            #pragma unroll
            for (int q = 0; q < 4; q++)
                xc2[u][q] = __shfl_xor_sync(0xffffffffu, sel ? cU[u][q] : cU[u+2][q], 4);

        // ---- publish x(t+1) to next buffer, then mid barrier ----
        if (t + 1 < S_) xstore(bnext);
        __syncthreads();

        // ---- issue x-part GEMM for t+1 (retires under the MUFU update below) ----
        if (t + 1 < S_) xpart(cA, nxtoff);
        if (t + 2 < S_) xpref(t + 2);

        // ---- update 4 cells ----
        __half* BhN = (__half*)bnext;
        __half* BlN = (__half*)(bnext + B_LOB);
        #pragma unroll
        for (int u = 0; u < 2; u++){
            #pragma unroll
            for (int pp = 0; pp < 2; pp++){
                float own0 = sel ? cU[u+2][pp]    : cU[u][pp];
                float own2 = sel ? cU[u+2][2+pp]  : cU[u][2+pp];
                float oth0 = xc2[u][pp];
                float oth2 = xc2[u][2+pp];
                float gi = (sel ? oth0 : own0) + bI;
                float gf = (sel ? own0 : oth0) + bF;
                float gg = (sel ? oth2 : own2) + bG;
                float go = (sel ? own2 : oth2) + bO;
                int li = u*2 + pp;
                float cc = sig_ps(gf)*cst[li] + sig_ps(gi)*tanhapx(gg);
                cst[li] = cc;
                float h = sig_ps(go)*tanhapx(cc);
                int col = colbase + u*8 + pp;
                __half hh = __float2half_rn(h);
                BhN[col*STRD + HOFF + jc] = hh;
                BlN[col*STRD + HOFF + jc] = __float2half_rn(h - __half2float(hh));
                if (ys) hbW[col*HBSTR + jc] = h;
                if (hf && t == S_-1) hf[(row0 + col)*H_ + jc] = h;
            }
        }
        __syncthreads();
    };

    for (int t = 0; t < S_; t += 2){
        stepf(t,     c0, c1);
        stepf(t + 1, c1, c0);
    }

    // final ys flush (step S-1 wrote hb[(S-1)&1] = HB1)
    if (ys){
        const float* hbR = (const float*)(smem + OFF_HB1);
        float4 v = *(const float4*)&hbR[frow*HBSTR + fc0];
        *(float4*)&ys[((size_t)(S_-1)*B_ + row0 + frow)*H_ + fc0] = v;
    }
}

__global__ void __launch_bounds__(512, 1) lstm_l0(
    const float* __restrict__ c_wih, const float* __restrict__ c_whh,
    const float* __restrict__ c_bih, const float* __restrict__ c_bhh,
    const float* __restrict__ v_wih, const float* __restrict__ v_whh,
    const float* __restrict__ v_bih, const float* __restrict__ v_bhh)
{
    extern __shared__ char smem[];
    if (blockIdx.x < 64)
        lstm_stream<2, 4, CC>(smem, g_convout, g_ys_cnn, nullptr, blockIdx.x*32,
                              c_wih, c_whh, c_bih, c_bhh);
    else
        lstm_stream<1, 4, DIN>(smem, g_xT, g_ys_vq, nullptr, (blockIdx.x-64)*32,
                               v_wih, v_whh, v_bih, v_bhh);
}

__global__ void __launch_bounds__(512, 1) lstm_l1(
    const float* __restrict__ c_wih, const float* __restrict__ c_whh,
    const float* __restrict__ c_bih, const float* __restrict__ c_bhh,
    const float* __restrict__ v_wih, const float* __restrict__ v_whh,
    const float* __restrict__ v_bih, const float* __restrict__ v_bhh)
{
    extern __shared__ char smem[];
    if (blockIdx.x < 64)
        lstm_stream<4, 4, H_>(smem, g_ys_cnn, nullptr, g_cnn_feat, blockIdx.x*32,
                              c_wih, c_whh, c_bih, c_bhh);
    else
        lstm_stream<4, 4, H_>(smem, g_ys_vq, nullptr, g_vq_hid, (blockIdx.x-64)*32,
                              v_wih, v_whh, v_bih, v_bhh);
}

// ---------------- VQ epilogue ----------------
__global__ void zero_k(){
    int t = threadIdx.x;
    if (t < NEMB) g_counts[t] = 0;
    if (t == 0)   g_sqsum = 0.f;
}

__global__ void vq_final(const float* __restrict__ proj_w, const float* __restrict__ proj_b,
                         const float* __restrict__ codebook, float* __restrict__ out)
{
    __shared__ float pw[EDIM*H_];
    __shared__ float pb[EDIM];
    __shared__ float cb[NEMB*EDIM];
    __shared__ float cn2[NEMB];
    __shared__ float red[256];
    int tid = threadIdx.x;
    for (int i = tid; i < EDIM*H_;   i += 256) pw[i] = proj_w[i];
    for (int i = tid; i < NEMB*EDIM; i += 256) cb[i] = codebook[i];
    if (tid < EDIM) pb[tid] = proj_b[tid];
    __syncthreads();
    if (tid < NEMB){
        float s = 0.f;
        #pragma unroll
        for (int e = 0; e < EDIM; e++){ float v = cb[tid*EDIM + e]; s = fmaf(v, v, s); }
        cn2[tid] = s;
    }
    __syncthreads();

    int b = blockIdx.x*256 + tid;
    float h[H_];
    const float4* hp = (const float4*)&g_vq_hid[b*H_];
    #pragma unroll
    for (int i = 0; i < H_/4; i++){
        float4 v = hp[i]; h[4*i] = v.x; h[4*i+1] = v.y; h[4*i+2] = v.z; h[4*i+3] = v.w;
    }
    float p[EDIM]; float p2 = 0.f;
    #pragma unroll
    for (int e = 0; e < EDIM; e++){
        float a = pb[e];
        #pragma unroll
        for (int d = 0; d < H_; d++) a = fmaf(pw[e*H_ + d], h[d], a);
        p[e] = a; p2 = fmaf(a, a, p2);
    }
    int best = 0; float dmin = 3.4e38f;
    #pragma unroll 4
    for (int n = 0; n < NEMB; n++){
        float dot = 0.f;
        #pragma unroll
        for (int e = 0; e < EDIM; e++) dot = fmaf(cb[n*EDIM + e], p[e], dot);
        float d = p2 + cn2[n] - 2.f*dot;
        if (d < dmin){ dmin = d; best = n; }
    }
    float rs = 0.f;
    #pragma unroll
    for (int e = 0; e < EDIM; e++){ float r = cb[best*EDIM + e] - p[e]; rs = fmaf(r, r, rs); }
    red[tid] = rs;
    atomicAdd(&g_counts[best], 1);

    const float* cf = &g_cnn_feat[b*H_];
    float* o0 = out + (size_t)b*96;
    float* o1 = out + (size_t)B_*96 + (size_t)b*96;
    #pragma unroll
    for (int jj = 0; jj < H_; jj++){ float v = cf[jj]; o0[jj] = v; o1[jj] = v; }
    #pragma unroll
    for (int e = 0; e < EDIM; e++){ float v = cb[best*EDIM + e]; o0[H_+e] = v; o1[H_+e] = v; }

    __syncthreads();
    for (int st = 128; st > 0; st >>= 1){
        if (tid < st) red[tid] += red[tid + st];
        __syncthreads();
    }
    if (tid == 0) atomicAdd(&g_sqsum, red[0]);
}

__global__ void finalize_k(float* __restrict__ out){
    if (threadIdx.x == 0){
        float msq = g_sqsum / (float)(B_*EDIM);
        out[(size_t)2*B_*96]     = msq + 0.01f * msq;
        float ent = 0.f;
        for (int n = 0; n < NEMB; n++){
            float ap = (float)g_counts[n] / (float)B_;
            ent += ap * logf(ap + 1e-10f);
        }
        out[(size_t)2*B_*96 + 1] = expf(-ent);
    }
}

// ---------------- launch ----------------
extern "C" void kernel_launch(void* const* d_in, const int* in_sizes, int n_in,
                              void* d_out, int out_size)
{
    const float* x       = (const float*)d_in[0];
    const float* conv_w  = (const float*)d_in[1];
    const float* conv_b  = (const float*)d_in[2];
    const float* bn_g    = (const float*)d_in[3];
    const float* bn_b    = (const float*)d_in[4];
    const float* bn_m    = (const float*)d_in[5];
    const float* bn_v    = (const float*)d_in[6];
    const float* c0_wih  = (const float*)d_in[7];
    const float* c0_whh  = (const float*)d_in[8];
    const float* c0_bih  = (const float*)d_in[9];
    const float* c0_bhh  = (const float*)d_in[10];
    const float* c1_wih  = (const float*)d_in[11];
    const float* c1_whh  = (const float*)d_in[12];
    const float* c1_bih  = (const float*)d_in[13];
    const float* c1_bhh  = (const float*)d_in[14];
    const float* v0_wih  = (const float*)d_in[15];
    const float* v0_whh  = (const float*)d_in[16];
    const float* v0_bih  = (const float*)d_in[17];
    const float* v0_bhh  = (const float*)d_in[18];
    const float* v1_wih  = (const float*)d_in[19];
    const float* v1_whh  = (const float*)d_in[20];
    const float* v1_bih  = (const float*)d_in[21];
    const float* v1_bhh  = (const float*)d_in[22];
    const float* proj_w  = (const float*)d_in[23];
    const float* proj_b  = (const float*)d_in[24];
    const float* codebook= (const float*)d_in[25];
    float* out = (float*)d_out;

    cudaFuncSetAttribute(lstm_l0, cudaFuncAttributeMaxDynamicSharedMemorySize, SMEM_TOT);
    cudaFuncSetAttribute(lstm_l1, cudaFuncAttributeMaxDynamicSharedMemorySize, SMEM_TOT);

    prep_kernel<<<(B_*S_)/256, 256>>>(x, conv_w, conv_b, bn_g, bn_b, bn_m, bn_v);
    zero_k<<<1, 64>>>();
    lstm_l0<<<128, 512, SMEM_TOT>>>(c0_wih, c0_whh, c0_bih, c0_bhh,
                                    v0_wih, v0_whh, v0_bih, v0_bhh);
    lstm_l1<<<128, 512, SMEM_TOT>>>(c1_wih, c1_whh, c1_bih, c1_bhh,
                                    v1_wih, v1_whh, v1_bih, v1_bhh);
    vq_final<<<B_/256, 256>>>(proj_w, proj_b, codebook, out);
    finalize_k<<<1, 64>>>(out);
}